// round 11
// baseline (speedup 1.0000x reference)
#include <cuda_runtime.h>
#include <cuda_fp16.h>
#include <math.h>
#include <stdint.h>

#define NL 4
#define NB 32
#define NH 512
#define NV 32000
#define NTT 51
#define NDIAG (NTT + NL - 1)
#define NBLK 288   // persistent grid: <= 296 co-resident (148 SMs x 2 @128regs)

typedef unsigned long long u64;

// ================= persistent device scratch =================
__device__ u64 g_x[2][NL][16][512];      // layer-input pairs (l>=1), ping-pong by t parity
__device__ u64 g_hb[2][NL][16][512];     // clamped hidden pairs, ping-pong by t parity
__device__ u64 g_c2[NL][16][512];        // clamped cell pairs
__device__ u64 g_emb2[NTT][16][512];     // pre-gathered embedding pairs per timestep

// fp16 operands for the projection (single pass); pad rows 1632..1663 stay 0
__device__ __half g_Hs[1664 * 512];
__device__ __half g_Ws[NV * 512];

// global barrier state (reset each call by init_pair)
__device__ int g_cnt[8 * 32];            // sub-counters, 128B apart
__device__ int g_root;
__device__ int g_flag;

// ================= helpers =================
__device__ __forceinline__ u64 pk2(float lo, float hi) {
    u64 r;
    asm("mov.b64 %0, {%1, %2};" : "=l"(r) : "r"(__float_as_uint(lo)), "r"(__float_as_uint(hi)));
    return r;
}
__device__ __forceinline__ void upk2(u64 v, float &lo, float &hi) {
    unsigned a, b;
    asm("mov.b64 {%0, %1}, %2;" : "=r"(a), "=r"(b) : "l"(v));
    lo = __uint_as_float(a); hi = __uint_as_float(b);
}
__device__ __forceinline__ u64 ffma2(u64 a, u64 b, u64 c) {
    u64 d;
    asm("fma.rn.f32x2 %0, %1, %2, %3;" : "=l"(d) : "l"(a), "l"(b), "l"(c));
    return d;
}
__device__ __forceinline__ u64 fadd2(u64 a, u64 b) {
    u64 d;
    asm("add.rn.f32x2 %0, %1, %2;" : "=l"(d) : "l"(a), "l"(b));
    return d;
}
__device__ __forceinline__ float sigmoidf_(float x) { return 1.0f / (1.0f + expf(-x)); }
__device__ __forceinline__ float clip50(float x) { return fminf(fmaxf(x, -50.0f), 50.0f); }

__device__ __forceinline__ int ldcg(const int* p) {
    int v;
    asm volatile("ld.global.cg.s32 %0, [%1];" : "=r"(v) : "l"(p));
    return v;
}

__device__ __forceinline__ uint32_t s2u(const void* p) {
    return (uint32_t)__cvta_generic_to_shared(p);
}
__device__ __forceinline__ void cpasync16(uint32_t dst, const void* src) {
    asm volatile("cp.async.cg.shared.global [%0], [%1], 16;" :: "r"(dst), "l"(src));
}
__device__ __forceinline__ void cp_commit() { asm volatile("cp.async.commit_group;" ::: "memory"); }
__device__ __forceinline__ void cp_wait1() { asm volatile("cp.async.wait_group 1;" ::: "memory"); }

#define LDMX4(r0, r1, r2, r3, a) \
    asm volatile("ldmatrix.sync.aligned.m8n8.x4.shared.b16 {%0,%1,%2,%3}, [%4];" \
                 : "=r"(r0), "=r"(r1), "=r"(r2), "=r"(r3) : "r"(a))

__device__ __forceinline__ void mma16816(float* d, const uint32_t* a, const uint32_t* b) {
    asm volatile("mma.sync.aligned.m16n8k16.row.col.f32.f16.f16.f32 "
                 "{%0,%1,%2,%3}, {%4,%5,%6,%7}, {%8,%9}, {%0,%1,%2,%3};"
                 : "+f"(d[0]), "+f"(d[1]), "+f"(d[2]), "+f"(d[3])
                 : "r"(a[0]), "r"(a[1]), "r"(a[2]), "r"(a[3]), "r"(b[0]), "r"(b[1]));
}

// ================= init kernels =================
__global__ void init_pair(const float* __restrict__ dh, const float* __restrict__ dc) {
    int idx = blockIdx.x * blockDim.x + threadIdx.x;   // 32768
    if (idx == 0) {                                     // reset barrier state each replay
        #pragma unroll
        for (int i = 0; i < 8; i++) g_cnt[i * 32] = 0;
        g_root = 0;
        g_flag = 0;
    }
    int l = idx >> 13, rem = idx & 8191, b2 = rem >> 9, j = rem & 511;
    int b0 = 2 * b2, b1 = b0 + 1;
    g_hb[0][l][b2][j] = pk2(dh[(l * 32 + b0) * 512 + j], dh[(l * 32 + b1) * 512 + j]);
    g_c2[l][b2][j]    = pk2(dc[(l * 32 + b0) * 512 + j], dc[(l * 32 + b1) * 512 + j]);
}

__global__ void init_emb(const float* __restrict__ emb, const int* __restrict__ target) {
    int idx = blockIdx.x * blockDim.x + threadIdx.x;   // 51*8192
    if (idx >= NTT * 8192) return;
    int t = idx >> 13, rem = idx & 8191, b2 = rem >> 9, k = rem & 511;
    int b0 = 2 * b2, b1 = b0 + 1;
    int t0 = (t == 0) ? 0 : target[b0 * NTT + t - 1];
    int t1 = (t == 0) ? 0 : target[b1 * NTT + t - 1];
    g_emb2[t][b2][k] = pk2(emb[t0 * 512 + k], emb[t1 * 512 + k]);
}

// round W_out to fp16 once
__global__ void conv_w(const float* __restrict__ W) {
    int idx = blockIdx.x * blockDim.x + threadIdx.x;   // 32000*64
    if (idx >= NV * 64) return;
    size_t base = (size_t)idx * 8;
    const float4* s = (const float4*)(W + base);
    float4 a = s[0], b = s[1];
    float v[8] = {a.x, a.y, a.z, a.w, b.x, b.y, b.z, b.w};
    __align__(16) __half h[8];
    #pragma unroll
    for (int i = 0; i < 8; i++) h[i] = __float2half_rn(v[i]);
    *(uint4*)&g_Ws[base] = *(const uint4*)h;
}

// ================= persistent wavefront LSTM =================
// ONE launch: NBLK blocks x 256 threads, co-resident (<=128 regs -> 2 blocks/SM).
// Per diagonal, all ns*256 stage-units are grid-stride-distributed over NBLK
// blocks; units are independent so per-block iterations pipeline.
__global__ __launch_bounds__(256, 2) void lstm_persist(
    const float* __restrict__ Wih, const float* __restrict__ Whh,
    const float* __restrict__ bih, const float* __restrict__ bhh)
{
    __shared__ u64 gates2[2 * 4 * 4 * 8];   // [khalf][gate][r][b2l] = 2KB

    const int u = blockIdx.x;
    const int tid = threadIdx.x, lane = tid & 31, wid = tid >> 5;
    const int khalf = wid & 1;
    const int gate  = (wid >> 1) & 3;
    const int sub = u & 7;

    for (int d = 0; d < NDIAG; d++) {
        const int lmin = (d > NTT - 1) ? d - (NTT - 1) : 0;
        const int lmax = (d < NL - 1) ? d : NL - 1;
        const int nun = (lmax - lmin + 1) * 256;

        for (int un = u; un < nun; un += NBLK) {
            const int l = lmin + (un >> 8);
            const int t = d - l;
            const int par = t & 1;
            const int within = un & 255;
            const int bhalf = within >> 7;
            const int j0 = (within & 127) * 4;

            const u64* xsrc = ((l == 0) ? &g_emb2[t][0][0] : &g_x[par][l][0][0]) + bhalf * 4096;
            const u64* hsrc = &g_hb[par][l][0][0] + bhalf * 4096;
            const u64* src  = (khalf ? hsrc : xsrc) + lane;

            const float* wp = (khalf ? Whh : Wih)
                + ((size_t)(l * 2048 + gate * 512 + j0)) * 512 + lane;

            // deep prefetch: 4 k-chunks of weights + 1 k-chunk of activations
            float wc[4][4];
            #pragma unroll
            for (int p = 0; p < 4; p++)
                #pragma unroll
                for (int r = 0; r < 4; r++) wc[p][r] = wp[r * 512 + p * 32];

            u64 xv[8];
            #pragma unroll
            for (int b = 0; b < 8; b++) xv[b] = src[b * 512];

            u64 acc[4][8];
            #pragma unroll
            for (int r = 0; r < 4; r++)
                #pragma unroll
                for (int b = 0; b < 8; b++) acc[r][b] = 0ULL;

            #pragma unroll
            for (int kc = 0; kc < 16; kc++) {
                const int sl = kc & 3;
                u64 aa[4];
                #pragma unroll
                for (int r = 0; r < 4; r++) aa[r] = pk2(wc[sl][r], wc[sl][r]);
                if (kc < 12) {
                    #pragma unroll
                    for (int r = 0; r < 4; r++) wc[sl][r] = wp[r * 512 + (kc + 4) * 32];
                }
                u64 xn[8];
                if (kc < 15) {
                    #pragma unroll
                    for (int b = 0; b < 8; b++) xn[b] = src[b * 512 + (kc + 1) * 32];
                }
                #pragma unroll
                for (int b = 0; b < 8; b++) {
                    #pragma unroll
                    for (int r = 0; r < 4; r++) acc[r][b] = ffma2(aa[r], xv[b], acc[r][b]);
                }
                if (kc < 15) {
                    #pragma unroll
                    for (int b = 0; b < 8; b++) xv[b] = xn[b];
                }
            }

            #pragma unroll
            for (int off = 16; off > 0; off >>= 1) {
                #pragma unroll
                for (int r = 0; r < 4; r++)
                    #pragma unroll
                    for (int b = 0; b < 8; b++)
                        acc[r][b] = fadd2(acc[r][b], __shfl_xor_sync(0xffffffffu, acc[r][b], off));
            }
            if (lane == 0) {
                #pragma unroll
                for (int r = 0; r < 4; r++)
                    #pragma unroll
                    for (int b = 0; b < 8; b++)
                        gates2[(((khalf * 4 + gate) * 4) + r) * 8 + b] = acc[r][b];
            }
            __syncthreads();

            // ---- pointwise epilogue: 4 j x 8 b2 = 32 threads ----
            if (tid < 32) {
                int jl = tid >> 3, b2l = tid & 7;
                int b2 = bhalf * 8 + b2l;
                int j = j0 + jl;
                float gv0[4], gv1[4];
                #pragma unroll
                for (int g = 0; g < 4; g++) {
                    u64 s = fadd2(gates2[((0 * 4 + g) * 4 + jl) * 8 + b2l],
                                  gates2[((1 * 4 + g) * 4 + jl) * 8 + b2l]);
                    float lo, hi; upk2(s, lo, hi);
                    float bb = bih[l * 2048 + g * 512 + j] + bhh[l * 2048 + g * 512 + j];
                    gv0[g] = lo + bb; gv1[g] = hi + bb;
                }
                float c0, c1; upk2(g_c2[l][b2][j], c0, c1);

                float i0 = sigmoidf_(gv0[0]), f0 = sigmoidf_(gv0[1]);
                float gg0 = tanhf(gv0[2]),   o0 = sigmoidf_(gv0[3]);
                float cn0 = f0 * c0 + i0 * gg0;
                float h0 = o0 * tanhf(cn0);

                float i1 = sigmoidf_(gv1[0]), f1 = sigmoidf_(gv1[1]);
                float gg1 = tanhf(gv1[2]),   o1 = sigmoidf_(gv1[3]);
                float cn1 = f1 * c1 + i1 * gg1;
                float h1 = o1 * tanhf(cn1);

                if (l < 3) {
                    g_x[par][l + 1][b2][j] = pk2(h0, h1);
                } else {
                    int b0 = 2 * b2;          // fp16 operand for the projection, direct
                    g_Hs[((size_t)t * 32 + b0) * 512 + j] = __float2half_rn(h0);
                    g_Hs[((size_t)t * 32 + b0 + 1) * 512 + j] = __float2half_rn(h1);
                }
                g_hb[par ^ 1][l][b2][j] = pk2(clip50(h0), clip50(h1));
                g_c2[l][b2][j] = pk2(clip50(cn0), clip50(cn1));
            }
            __syncthreads();
        }

        // ---- hierarchical global barrier between diagonals ----
        if (d < NDIAG - 1) {
            if (tid == 0) {
                __threadfence();
                int old = atomicAdd(&g_cnt[sub * 32], 1);
                if (old == d * 36 + 35) {          // 36 blocks per sub-counter
                    int r = atomicAdd(&g_root, 1);
                    if (r == d * 8 + 7) {
                        atomicExch(&g_flag, d + 1);
                    }
                }
                while (ldcg(&g_flag) < d + 1) __nanosleep(64);
                __threadfence();
            }
            __syncthreads();
        }
    }
}

// ================= mma.sync fp16 projection (single pass) =================
// C[1664,32000] = A @ W^T, K=512 (8 chunks of 64).
// BM=BN=128, BK=64 (128B rows, XOR swizzle), 8 warps (4m x 2n), warp tile 32x64.
__global__ __launch_bounds__(256) void proj_mma(
    const float* __restrict__ bout, float* __restrict__ out)
{
    extern __shared__ __align__(16) unsigned char ps[];
    const uint32_t sb = s2u(ps);
    const int tid = threadIdx.x, lane = tid & 31, wid = tid >> 5;
    const int wm = wid & 3, wn = wid >> 2;
    const int bm = blockIdx.y * 128, bn = blockIdx.x * 128;

    const uint32_t Ab[2] = {sb, sb + 16384};
    const uint32_t Bb[2] = {sb + 32768, sb + 49152};

    float acc[2][8][4];
    #pragma unroll
    for (int f = 0; f < 2; f++)
        #pragma unroll
        for (int p = 0; p < 8; p++)
            #pragma unroll
            for (int q = 0; q < 4; q++) acc[f][p][q] = 0.0f;

    const int sr = tid >> 3, su = tid & 7;

    // prologue: chunk 0
    #pragma unroll
    for (int i = 0; i < 4; i++) {
        int r = sr + i * 32;
        cpasync16(Ab[0] + r * 128 + ((su ^ (r & 7)) << 4),
                  g_Hs + (size_t)(bm + r) * 512 + su * 8);
        cpasync16(Bb[0] + r * 128 + ((su ^ (r & 7)) << 4),
                  g_Ws + (size_t)(bn + r) * 512 + su * 8);
    }
    cp_commit();

    for (int c = 0; c < 8; c++) {
        if (c + 1 < 8) {
            int k0 = (c + 1) * 64;
            uint32_t da = Ab[(c + 1) & 1], db = Bb[(c + 1) & 1];
            #pragma unroll
            for (int i = 0; i < 4; i++) {
                int r = sr + i * 32;
                cpasync16(da + r * 128 + ((su ^ (r & 7)) << 4),
                          g_Hs + (size_t)(bm + r) * 512 + k0 + su * 8);
                cpasync16(db + r * 128 + ((su ^ (r & 7)) << 4),
                          g_Ws + (size_t)(bn + r) * 512 + k0 + su * 8);
            }
        }
        cp_commit();
        cp_wait1();
        __syncthreads();

        const uint32_t Abase = Ab[c & 1], Bbase = Bb[c & 1];
        const int jA = lane >> 3;
        #pragma unroll
        for (int q = 0; q < 4; q++) {
            uint32_t a[2][4];
            #pragma unroll
            for (int f = 0; f < 2; f++) {
                int r = wm * 32 + f * 16 + (lane & 7) + ((jA & 1) << 3);
                int uu = 2 * q + (jA >> 1);
                uint32_t ad = Abase + r * 128 + ((uu ^ (r & 7)) << 4);
                LDMX4(a[f][0], a[f][1], a[f][2], a[f][3], ad);
            }
            uint32_t b[8][2];
            #pragma unroll
            for (int fp = 0; fp < 4; fp++) {
                int r = wn * 64 + fp * 16 + (lane & 7) + ((jA >> 1) << 3);
                int uu = 2 * q + (jA & 1);
                uint32_t bd = Bbase + r * 128 + ((uu ^ (r & 7)) << 4);
                LDMX4(b[2 * fp][0], b[2 * fp][1], b[2 * fp + 1][0], b[2 * fp + 1][1], bd);
            }
            #pragma unroll
            for (int f = 0; f < 2; f++)
                #pragma unroll
                for (int p = 0; p < 8; p++)
                    mma16816(acc[f][p], a[f], b[p]);
        }
        __syncthreads();
    }

    // epilogue: C[m][n] + bias, remap m=(t*32+b) -> out[b][t][:]
    #pragma unroll
    for (int f = 0; f < 2; f++) {
        int m0 = bm + wm * 32 + f * 16 + (lane >> 2);
        #pragma unroll
        for (int p = 0; p < 8; p++) {
            int n = bn + wn * 64 + p * 8 + 2 * (lane & 3);
            float2 bo = *(const float2*)&bout[n];
            int m = m0;
            if (m < 1632) {
                int tt = m >> 5, b = m & 31;
                float2 r0 = make_float2(acc[f][p][0] + bo.x, acc[f][p][1] + bo.y);
                *(float2*)&out[(size_t)b * NTT * NV + (size_t)tt * NV + n] = r0;
            }
            m = m0 + 8;
            if (m < 1632) {
                int tt = m >> 5, b = m & 31;
                float2 r1 = make_float2(acc[f][p][2] + bo.x, acc[f][p][3] + bo.y);
                *(float2*)&out[(size_t)b * NTT * NV + (size_t)tt * NV + n] = r1;
            }
        }
    }
}

// ================= final hidden state tail =================
__global__ void write_hfin(float* __restrict__ out) {
    int idx = blockIdx.x * blockDim.x + threadIdx.x;   // 65536
    int l = idx >> 14, b = (idx >> 9) & 31, j = idx & 511;
    float lo, hi; upk2(g_hb[1][l][b >> 1][j], lo, hi);
    out[(size_t)NB * NTT * NV + idx] = (b & 1) ? hi : lo;
}

extern "C" void kernel_launch(void* const* d_in, const int* in_sizes, int n_in,
                              void* d_out, int out_size)
{
    (void)in_sizes; (void)n_in; (void)out_size;
    const float* dh   = (const float*)d_in[1];
    const float* dc   = (const float*)d_in[2];
    const int*   tgt  = (const int*)  d_in[3];
    const float* emb  = (const float*)d_in[4];
    const float* Wih  = (const float*)d_in[5];
    const float* Whh  = (const float*)d_in[6];
    const float* bih  = (const float*)d_in[7];
    const float* bhh  = (const float*)d_in[8];
    const float* Wout = (const float*)d_in[9];
    const float* bout = (const float*)d_in[10];
    float* out = (float*)d_out;

    const int SMEM_PROJ = 65536;
    cudaFuncSetAttribute(proj_mma, cudaFuncAttributeMaxDynamicSharedMemorySize, SMEM_PROJ);

    init_pair<<<128, 256>>>(dh, dc);
    init_emb<<<1632, 256>>>(emb, tgt);
    conv_w<<<8000, 256>>>(Wout);

    lstm_persist<<<NBLK, 256>>>(Wih, Whh, bih, bhh);

    proj_mma<<<dim3(250, 13), 256, SMEM_PROJ>>>(bout, out);
    write_hfin<<<256, 256>>>(out);
}

// round 12
// speedup vs baseline: 1.1421x; 1.1421x over previous
#include <cuda_runtime.h>
#include <cuda_fp16.h>
#include <math.h>
#include <stdint.h>

#define NL 4
#define NB 32
#define NH 512
#define NV 32000
#define NTT 51
#define NDIAG (NTT + NL - 1)

typedef unsigned long long u64;

// ================= persistent device scratch =================
__device__ u64 g_x[2][NL][16][512];      // layer-input pairs (l>=1), ping-pong by t parity
__device__ u64 g_hb[2][NL][16][512];     // clamped hidden pairs, ping-pong by t parity
__device__ u64 g_c2[NL][16][512];        // clamped cell pairs
__device__ u64 g_emb2[NTT][16][512];     // pre-gathered embedding pairs per timestep

// fp16 operands for the projection (single pass); pad rows 1632..1663 stay 0
__device__ __half g_Hs[1664 * 512];
__device__ __half g_Ws[NV * 512];

// ================= helpers =================
__device__ __forceinline__ u64 pk2(float lo, float hi) {
    u64 r;
    asm("mov.b64 %0, {%1, %2};" : "=l"(r) : "r"(__float_as_uint(lo)), "r"(__float_as_uint(hi)));
    return r;
}
__device__ __forceinline__ u64 pku(unsigned lo, unsigned hi) {
    u64 r;
    asm("mov.b64 %0, {%1, %2};" : "=l"(r) : "r"(lo), "r"(hi));
    return r;
}
__device__ __forceinline__ void upk2(u64 v, float &lo, float &hi) {
    unsigned a, b;
    asm("mov.b64 {%0, %1}, %2;" : "=r"(a), "=r"(b) : "l"(v));
    lo = __uint_as_float(a); hi = __uint_as_float(b);
}
__device__ __forceinline__ u64 ffma2(u64 a, u64 b, u64 c) {
    u64 d;
    asm("fma.rn.f32x2 %0, %1, %2, %3;" : "=l"(d) : "l"(a), "l"(b), "l"(c));
    return d;
}
__device__ __forceinline__ u64 fadd2(u64 a, u64 b) {
    u64 d;
    asm("add.rn.f32x2 %0, %1, %2;" : "=l"(d) : "l"(a), "l"(b));
    return d;
}
__device__ __forceinline__ float sigmoidf_(float x) { return 1.0f / (1.0f + expf(-x)); }
__device__ __forceinline__ float clip50(float x) { return fminf(fmaxf(x, -50.0f), 50.0f); }

__device__ __forceinline__ uint32_t s2u(const void* p) {
    return (uint32_t)__cvta_generic_to_shared(p);
}
__device__ __forceinline__ void cpasync16(uint32_t dst, const void* src) {
    asm volatile("cp.async.cg.shared.global [%0], [%1], 16;" :: "r"(dst), "l"(src));
}
__device__ __forceinline__ void cp_commit() { asm volatile("cp.async.commit_group;" ::: "memory"); }
__device__ __forceinline__ void cp_wait1() { asm volatile("cp.async.wait_group 1;" ::: "memory"); }

#define LDMX4(r0, r1, r2, r3, a) \
    asm volatile("ldmatrix.sync.aligned.m8n8.x4.shared.b16 {%0,%1,%2,%3}, [%4];" \
                 : "=r"(r0), "=r"(r1), "=r"(r2), "=r"(r3) : "r"(a))

__device__ __forceinline__ void mma16816(float* d, const uint32_t* a, const uint32_t* b) {
    asm volatile("mma.sync.aligned.m16n8k16.row.col.f32.f16.f16.f32 "
                 "{%0,%1,%2,%3}, {%4,%5,%6,%7}, {%8,%9}, {%0,%1,%2,%3};"
                 : "+f"(d[0]), "+f"(d[1]), "+f"(d[2]), "+f"(d[3])
                 : "r"(a[0]), "r"(a[1]), "r"(a[2]), "r"(a[3]), "r"(b[0]), "r"(b[1]));
}

// ================= init kernels =================
__global__ void init_pair(const float* __restrict__ dh, const float* __restrict__ dc) {
    int idx = blockIdx.x * blockDim.x + threadIdx.x;   // 32768
    int l = idx >> 13, rem = idx & 8191, b2 = rem >> 9, j = rem & 511;
    int b0 = 2 * b2, b1 = b0 + 1;
    g_hb[0][l][b2][j] = pk2(dh[(l * 32 + b0) * 512 + j], dh[(l * 32 + b1) * 512 + j]);
    g_c2[l][b2][j]    = pk2(dc[(l * 32 + b0) * 512 + j], dc[(l * 32 + b1) * 512 + j]);
}

__global__ void init_emb(const float* __restrict__ emb, const int* __restrict__ target) {
    int idx = blockIdx.x * blockDim.x + threadIdx.x;   // 51*8192
    if (idx >= NTT * 8192) return;
    int t = idx >> 13, rem = idx & 8191, b2 = rem >> 9, k = rem & 511;
    int b0 = 2 * b2, b1 = b0 + 1;
    int t0 = (t == 0) ? 0 : target[b0 * NTT + t - 1];
    int t1 = (t == 0) ? 0 : target[b1 * NTT + t - 1];
    g_emb2[t][b2][k] = pk2(emb[t0 * 512 + k], emb[t1 * 512 + k]);
}

// round W_out to fp16 once
__global__ void conv_w(const float* __restrict__ W) {
    int idx = blockIdx.x * blockDim.x + threadIdx.x;   // 32000*64
    if (idx >= NV * 64) return;
    size_t base = (size_t)idx * 8;
    const float4* s = (const float4*)(W + base);
    float4 a = s[0], b = s[1];
    float v[8] = {a.x, a.y, a.z, a.w, b.x, b.y, b.z, b.w};
    __align__(16) __half h[8];
    #pragma unroll
    for (int i = 0; i < 8; i++) h[i] = __float2half_rn(v[i]);
    *(uint4*)&g_Ws[base] = *(const uint4*)h;
}

// ================= wavefront LSTM (multi-launch, R8 structure) =================
// Per stage: 256 blocks (128 j-tiles x 2 batch-halves), 256 threads (8 warps).
// Warp = (khalf, gate): 4 rows x 8 batch-pairs. 8 k-chunks of 64; lane covers
// k = {2*lane, 2*lane+1} within a chunk. x via LDG.128, W via LDG.64 (depth-2).
__global__ __launch_bounds__(256, 2) void lstm_diag(
    int d,
    const float* __restrict__ Wih, const float* __restrict__ Whh,
    const float* __restrict__ bih, const float* __restrict__ bhh)
{
    __shared__ u64 gates2[2 * 4 * 4 * 8];   // [khalf][gate][r][b2l] = 2KB

    const int lmin = (d > NTT - 1) ? d - (NTT - 1) : 0;
    const int within = blockIdx.x & 255;
    const int l = lmin + (blockIdx.x >> 8);
    const int t = d - l;
    const int par = t & 1;
    const int bhalf = within >> 7;
    const int j0 = (within & 127) * 4;
    const int tid = threadIdx.x, lane = tid & 31, wid = tid >> 5;

    const int khalf = wid & 1;
    const int gate  = (wid >> 1) & 3;

    const u64* xsrc = ((l == 0) ? &g_emb2[t][0][0] : &g_x[par][l][0][0]) + bhalf * 4096;
    const u64* hsrc = &g_hb[par][l][0][0] + bhalf * 4096;
    const uint4* src4 = (const uint4*)(khalf ? hsrc : xsrc) + lane;   // b slab = 256 uint4

    // W as float2: row stride 256 float2, chunk stride 32 float2
    const float2* wp2 = (const float2*)((khalf ? Whh : Wih)
        + ((size_t)(l * 2048 + gate * 512 + j0)) * 512) + lane;

    // depth-2 W prefetch
    float2 wc[2][4];
    #pragma unroll
    for (int p = 0; p < 2; p++)
        #pragma unroll
        for (int r = 0; r < 4; r++) wc[p][r] = wp2[r * 256 + p * 32];

    u64 acc[4][8];
    #pragma unroll
    for (int r = 0; r < 4; r++)
        #pragma unroll
        for (int b = 0; b < 8; b++) acc[r][b] = 0ULL;

    #pragma unroll
    for (int kc = 0; kc < 8; kc++) {
        const int sl = kc & 1;
        u64 ak0[4], ak1[4];
        #pragma unroll
        for (int r = 0; r < 4; r++) {
            ak0[r] = pk2(wc[sl][r].x, wc[sl][r].x);
            ak1[r] = pk2(wc[sl][r].y, wc[sl][r].y);
        }
        if (kc < 6) {
            #pragma unroll
            for (int r = 0; r < 4; r++) wc[sl][r] = wp2[r * 256 + (kc + 2) * 32];
        }
        #pragma unroll
        for (int b = 0; b < 8; b++) {
            uint4 x4 = src4[b * 256 + kc * 32];
            u64 xlo = pku(x4.x, x4.y);
            u64 xhi = pku(x4.z, x4.w);
            #pragma unroll
            for (int r = 0; r < 4; r++) {
                acc[r][b] = ffma2(ak0[r], xlo, acc[r][b]);
                acc[r][b] = ffma2(ak1[r], xhi, acc[r][b]);
            }
        }
    }

    #pragma unroll
    for (int off = 16; off > 0; off >>= 1) {
        #pragma unroll
        for (int r = 0; r < 4; r++)
            #pragma unroll
            for (int b = 0; b < 8; b++)
                acc[r][b] = fadd2(acc[r][b], __shfl_xor_sync(0xffffffffu, acc[r][b], off));
    }
    if (lane == 0) {
        #pragma unroll
        for (int r = 0; r < 4; r++)
            #pragma unroll
            for (int b = 0; b < 8; b++)
                gates2[(((khalf * 4 + gate) * 4) + r) * 8 + b] = acc[r][b];
    }
    __syncthreads();

    // ---- pointwise epilogue: 4 j x 8 b2 = 32 threads ----
    if (tid < 32) {
        int jl = tid >> 3, b2l = tid & 7;
        int b2 = bhalf * 8 + b2l;
        int j = j0 + jl;
        float gv0[4], gv1[4];
        #pragma unroll
        for (int g = 0; g < 4; g++) {
            u64 s = fadd2(gates2[((0 * 4 + g) * 4 + jl) * 8 + b2l],
                          gates2[((1 * 4 + g) * 4 + jl) * 8 + b2l]);
            float lo, hi; upk2(s, lo, hi);
            float bb = bih[l * 2048 + g * 512 + j] + bhh[l * 2048 + g * 512 + j];
            gv0[g] = lo + bb; gv1[g] = hi + bb;
        }
        float c0, c1; upk2(g_c2[l][b2][j], c0, c1);

        float i0 = sigmoidf_(gv0[0]), f0 = sigmoidf_(gv0[1]);
        float gg0 = tanhf(gv0[2]),   o0 = sigmoidf_(gv0[3]);
        float cn0 = f0 * c0 + i0 * gg0;
        float h0 = o0 * tanhf(cn0);

        float i1 = sigmoidf_(gv1[0]), f1 = sigmoidf_(gv1[1]);
        float gg1 = tanhf(gv1[2]),   o1 = sigmoidf_(gv1[3]);
        float cn1 = f1 * c1 + i1 * gg1;
        float h1 = o1 * tanhf(cn1);

        if (l < 3) {
            g_x[par][l + 1][b2][j] = pk2(h0, h1);
        } else {
            int b0 = 2 * b2;                         // fp16 operand for proj, direct
            g_Hs[((size_t)t * 32 + b0) * 512 + j] = __float2half_rn(h0);
            g_Hs[((size_t)t * 32 + b0 + 1) * 512 + j] = __float2half_rn(h1);
        }
        g_hb[par ^ 1][l][b2][j] = pk2(clip50(h0), clip50(h1));
        g_c2[l][b2][j] = pk2(clip50(cn0), clip50(cn1));
    }
}

// ================= mma.sync fp16 projection (single pass) =================
// C[1664,32000] = A @ W^T, K=512 (8 chunks of 64).
// BM=BN=128, BK=64 (128B rows, XOR swizzle), 8 warps (4m x 2n), warp tile 32x64.
__global__ __launch_bounds__(256) void proj_mma(
    const float* __restrict__ bout, float* __restrict__ out)
{
    extern __shared__ __align__(16) unsigned char ps[];
    const uint32_t sb = s2u(ps);
    const int tid = threadIdx.x, lane = tid & 31, wid = tid >> 5;
    const int wm = wid & 3, wn = wid >> 2;
    const int bm = blockIdx.y * 128, bn = blockIdx.x * 128;

    const uint32_t Ab[2] = {sb, sb + 16384};
    const uint32_t Bb[2] = {sb + 32768, sb + 49152};

    float acc[2][8][4];
    #pragma unroll
    for (int f = 0; f < 2; f++)
        #pragma unroll
        for (int p = 0; p < 8; p++)
            #pragma unroll
            for (int q = 0; q < 4; q++) acc[f][p][q] = 0.0f;

    const int sr = tid >> 3, su = tid & 7;

    // prologue: chunk 0
    #pragma unroll
    for (int i = 0; i < 4; i++) {
        int r = sr + i * 32;
        cpasync16(Ab[0] + r * 128 + ((su ^ (r & 7)) << 4),
                  g_Hs + (size_t)(bm + r) * 512 + su * 8);
        cpasync16(Bb[0] + r * 128 + ((su ^ (r & 7)) << 4),
                  g_Ws + (size_t)(bn + r) * 512 + su * 8);
    }
    cp_commit();

    for (int c = 0; c < 8; c++) {
        if (c + 1 < 8) {
            int k0 = (c + 1) * 64;
            uint32_t da = Ab[(c + 1) & 1], db = Bb[(c + 1) & 1];
            #pragma unroll
            for (int i = 0; i < 4; i++) {
                int r = sr + i * 32;
                cpasync16(da + r * 128 + ((su ^ (r & 7)) << 4),
                          g_Hs + (size_t)(bm + r) * 512 + k0 + su * 8);
                cpasync16(db + r * 128 + ((su ^ (r & 7)) << 4),
                          g_Ws + (size_t)(bn + r) * 512 + k0 + su * 8);
            }
        }
        cp_commit();
        cp_wait1();
        __syncthreads();

        const uint32_t Abase = Ab[c & 1], Bbase = Bb[c & 1];
        const int jA = lane >> 3;
        #pragma unroll
        for (int q = 0; q < 4; q++) {
            uint32_t a[2][4];
            #pragma unroll
            for (int f = 0; f < 2; f++) {
                int r = wm * 32 + f * 16 + (lane & 7) + ((jA & 1) << 3);
                int uu = 2 * q + (jA >> 1);
                uint32_t ad = Abase + r * 128 + ((uu ^ (r & 7)) << 4);
                LDMX4(a[f][0], a[f][1], a[f][2], a[f][3], ad);
            }
            uint32_t b[8][2];
            #pragma unroll
            for (int fp = 0; fp < 4; fp++) {
                int r = wn * 64 + fp * 16 + (lane & 7) + ((jA >> 1) << 3);
                int uu = 2 * q + (jA & 1);
                uint32_t bd = Bbase + r * 128 + ((uu ^ (r & 7)) << 4);
                LDMX4(b[2 * fp][0], b[2 * fp][1], b[2 * fp + 1][0], b[2 * fp + 1][1], bd);
            }
            #pragma unroll
            for (int f = 0; f < 2; f++)
                #pragma unroll
                for (int p = 0; p < 8; p++)
                    mma16816(acc[f][p], a[f], b[p]);
        }
        __syncthreads();
    }

    // epilogue: C[m][n] + bias, remap m=(t*32+b) -> out[b][t][:]
    #pragma unroll
    for (int f = 0; f < 2; f++) {
        int m0 = bm + wm * 32 + f * 16 + (lane >> 2);
        #pragma unroll
        for (int p = 0; p < 8; p++) {
            int n = bn + wn * 64 + p * 8 + 2 * (lane & 3);
            float2 bo = *(const float2*)&bout[n];
            int m = m0;
            if (m < 1632) {
                int tt = m >> 5, b = m & 31;
                float2 r0 = make_float2(acc[f][p][0] + bo.x, acc[f][p][1] + bo.y);
                *(float2*)&out[(size_t)b * NTT * NV + (size_t)tt * NV + n] = r0;
            }
            m = m0 + 8;
            if (m < 1632) {
                int tt = m >> 5, b = m & 31;
                float2 r1 = make_float2(acc[f][p][2] + bo.x, acc[f][p][3] + bo.y);
                *(float2*)&out[(size_t)b * NTT * NV + (size_t)tt * NV + n] = r1;
            }
        }
    }
}

// ================= final hidden state tail =================
__global__ void write_hfin(float* __restrict__ out) {
    int idx = blockIdx.x * blockDim.x + threadIdx.x;   // 65536
    int l = idx >> 14, b = (idx >> 9) & 31, j = idx & 511;
    float lo, hi; upk2(g_hb[1][l][b >> 1][j], lo, hi);
    out[(size_t)NB * NTT * NV + idx] = (b & 1) ? hi : lo;
}

extern "C" void kernel_launch(void* const* d_in, const int* in_sizes, int n_in,
                              void* d_out, int out_size)
{
    (void)in_sizes; (void)n_in; (void)out_size;
    const float* dh   = (const float*)d_in[1];
    const float* dc   = (const float*)d_in[2];
    const int*   tgt  = (const int*)  d_in[3];
    const float* emb  = (const float*)d_in[4];
    const float* Wih  = (const float*)d_in[5];
    const float* Whh  = (const float*)d_in[6];
    const float* bih  = (const float*)d_in[7];
    const float* bhh  = (const float*)d_in[8];
    const float* Wout = (const float*)d_in[9];
    const float* bout = (const float*)d_in[10];
    float* out = (float*)d_out;

    const int SMEM_PROJ = 65536;
    cudaFuncSetAttribute(proj_mma, cudaFuncAttributeMaxDynamicSharedMemorySize, SMEM_PROJ);

    init_pair<<<128, 256>>>(dh, dc);
    init_emb<<<1632, 256>>>(emb, tgt);
    conv_w<<<8000, 256>>>(Wout);

    for (int d = 0; d < NDIAG; d++) {
        int lmin = (d > NTT - 1) ? d - (NTT - 1) : 0;
        int lmax = (d < NL - 1) ? d : NL - 1;
        int ns = lmax - lmin + 1;
        lstm_diag<<<256 * ns, 256>>>(d, Wih, Whh, bih, bhh);
    }

    proj_mma<<<dim3(250, 13), 256, SMEM_PROJ>>>(bout, out);
    write_hfin<<<256, 256>>>(out);
}

// round 13
// speedup vs baseline: 1.1884x; 1.0405x over previous
#include <cuda_runtime.h>
#include <cuda_fp16.h>
#include <math.h>
#include <stdint.h>

#define NL 4
#define NB 32
#define NH 512
#define NV 32000
#define NTT 51
#define NDIAG (NTT + NL - 1)

typedef unsigned long long u64;

// ================= persistent device scratch =================
__device__ u64 g_x[2][NL][16][512];      // layer-input pairs (l>=1), ping-pong by t parity
__device__ u64 g_hb[2][NL][16][512];     // clamped hidden pairs, ping-pong by t parity
__device__ u64 g_c2[NL][16][512];        // clamped cell pairs
__device__ u64 g_emb2[NTT][16][512];     // pre-gathered embedding pairs per timestep

// fp16 operands for the projection (single pass); pad rows 1632..1663 stay 0
__device__ __half g_Hs[1664 * 512];
__device__ __half g_Ws[NV * 512];

// ================= helpers =================
__device__ __forceinline__ u64 pk2(float lo, float hi) {
    u64 r;
    asm("mov.b64 %0, {%1, %2};" : "=l"(r) : "r"(__float_as_uint(lo)), "r"(__float_as_uint(hi)));
    return r;
}
__device__ __forceinline__ void upk2(u64 v, float &lo, float &hi) {
    unsigned a, b;
    asm("mov.b64 {%0, %1}, %2;" : "=r"(a), "=r"(b) : "l"(v));
    lo = __uint_as_float(a); hi = __uint_as_float(b);
}
__device__ __forceinline__ u64 ffma2(u64 a, u64 b, u64 c) {
    u64 d;
    asm("fma.rn.f32x2 %0, %1, %2, %3;" : "=l"(d) : "l"(a), "l"(b), "l"(c));
    return d;
}
__device__ __forceinline__ u64 fadd2(u64 a, u64 b) {
    u64 d;
    asm("add.rn.f32x2 %0, %1, %2;" : "=l"(d) : "l"(a), "l"(b));
    return d;
}
__device__ __forceinline__ float sigmoidf_(float x) { return 1.0f / (1.0f + expf(-x)); }
__device__ __forceinline__ float clip50(float x) { return fminf(fmaxf(x, -50.0f), 50.0f); }

__device__ __forceinline__ uint32_t s2u(const void* p) {
    return (uint32_t)__cvta_generic_to_shared(p);
}
__device__ __forceinline__ void cpasync16(uint32_t dst, const void* src) {
    asm volatile("cp.async.cg.shared.global [%0], [%1], 16;" :: "r"(dst), "l"(src));
}
__device__ __forceinline__ void cp_commit() { asm volatile("cp.async.commit_group;" ::: "memory"); }
__device__ __forceinline__ void cp_wait1() { asm volatile("cp.async.wait_group 1;" ::: "memory"); }

#define LDMX4(r0, r1, r2, r3, a) \
    asm volatile("ldmatrix.sync.aligned.m8n8.x4.shared.b16 {%0,%1,%2,%3}, [%4];" \
                 : "=r"(r0), "=r"(r1), "=r"(r2), "=r"(r3) : "r"(a))

__device__ __forceinline__ void mma16816(float* d, const uint32_t* a, const uint32_t* b) {
    asm volatile("mma.sync.aligned.m16n8k16.row.col.f32.f16.f16.f32 "
                 "{%0,%1,%2,%3}, {%4,%5,%6,%7}, {%8,%9}, {%0,%1,%2,%3};"
                 : "+f"(d[0]), "+f"(d[1]), "+f"(d[2]), "+f"(d[3])
                 : "r"(a[0]), "r"(a[1]), "r"(a[2]), "r"(a[3]), "r"(b[0]), "r"(b[1]));
}

// ================= init kernels =================
__global__ void init_pair(const float* __restrict__ dh, const float* __restrict__ dc) {
    int idx = blockIdx.x * blockDim.x + threadIdx.x;   // 32768
    int l = idx >> 13, rem = idx & 8191, b2 = rem >> 9, j = rem & 511;
    int b0 = 2 * b2, b1 = b0 + 1;
    g_hb[0][l][b2][j] = pk2(dh[(l * 32 + b0) * 512 + j], dh[(l * 32 + b1) * 512 + j]);
    g_c2[l][b2][j]    = pk2(dc[(l * 32 + b0) * 512 + j], dc[(l * 32 + b1) * 512 + j]);
}

__global__ void init_emb(const float* __restrict__ emb, const int* __restrict__ target) {
    int idx = blockIdx.x * blockDim.x + threadIdx.x;   // 51*8192
    if (idx >= NTT * 8192) return;
    int t = idx >> 13, rem = idx & 8191, b2 = rem >> 9, k = rem & 511;
    int b0 = 2 * b2, b1 = b0 + 1;
    int t0 = (t == 0) ? 0 : target[b0 * NTT + t - 1];
    int t1 = (t == 0) ? 0 : target[b1 * NTT + t - 1];
    g_emb2[t][b2][k] = pk2(emb[t0 * 512 + k], emb[t1 * 512 + k]);
}

// round W_out to fp16 once
__global__ void conv_w(const float* __restrict__ W) {
    int idx = blockIdx.x * blockDim.x + threadIdx.x;   // 32000*64
    if (idx >= NV * 64) return;
    size_t base = (size_t)idx * 8;
    const float4* s = (const float4*)(W + base);
    float4 a = s[0], b = s[1];
    float v[8] = {a.x, a.y, a.z, a.w, b.x, b.y, b.z, b.w};
    __align__(16) __half h[8];
    #pragma unroll
    for (int i = 0; i < 8; i++) h[i] = __float2half_rn(v[i]);
    *(uint4*)&g_Ws[base] = *(const uint4*)h;
}

// ================= wavefront LSTM (R8-proven configuration) =================
// Per stage: 256 blocks (128 j-tiles x 2 batch-halves), 256 threads (8 warps).
// No SMEM staging: x/h read straight from global through L1 (64KB slab, 8x reuse).
// Warp = (khalf, gate): 4 rows x 8 batch-pairs, lane-split K by 32,
// weight prefetch depth 4, x prefetch depth 1.
__global__ __launch_bounds__(256, 2) void lstm_diag(
    int d,
    const float* __restrict__ Wih, const float* __restrict__ Whh,
    const float* __restrict__ bih, const float* __restrict__ bhh)
{
    __shared__ u64 gates2[2 * 4 * 4 * 8];   // [khalf][gate][r][b2l] = 2KB

    const int lmin = (d > NTT - 1) ? d - (NTT - 1) : 0;
    const int within = blockIdx.x & 255;
    const int l = lmin + (blockIdx.x >> 8);
    const int t = d - l;
    const int par = t & 1;
    const int bhalf = within >> 7;
    const int j0 = (within & 127) * 4;
    const int tid = threadIdx.x, lane = tid & 31, wid = tid >> 5;

    const int khalf = wid & 1;
    const int gate  = (wid >> 1) & 3;

    const u64* xsrc = ((l == 0) ? &g_emb2[t][0][0] : &g_x[par][l][0][0]) + bhalf * 4096;
    const u64* hsrc = &g_hb[par][l][0][0] + bhalf * 4096;
    const u64* src  = (khalf ? hsrc : xsrc) + lane;

    const float* wp = (khalf ? Whh : Wih)
        + ((size_t)(l * 2048 + gate * 512 + j0)) * 512 + lane;

    // deep prefetch: 4 k-chunks of weights + 1 k-chunk of activations
    float wc[4][4];
    #pragma unroll
    for (int p = 0; p < 4; p++)
        #pragma unroll
        for (int r = 0; r < 4; r++) wc[p][r] = wp[r * 512 + p * 32];

    u64 xv[8];
    #pragma unroll
    for (int b = 0; b < 8; b++) xv[b] = src[b * 512];

    u64 acc[4][8];
    #pragma unroll
    for (int r = 0; r < 4; r++)
        #pragma unroll
        for (int b = 0; b < 8; b++) acc[r][b] = 0ULL;

    #pragma unroll
    for (int kc = 0; kc < 16; kc++) {
        const int sl = kc & 3;
        u64 aa[4];
        #pragma unroll
        for (int r = 0; r < 4; r++) aa[r] = pk2(wc[sl][r], wc[sl][r]);
        if (kc < 12) {
            #pragma unroll
            for (int r = 0; r < 4; r++) wc[sl][r] = wp[r * 512 + (kc + 4) * 32];
        }
        u64 xn[8];
        if (kc < 15) {
            #pragma unroll
            for (int b = 0; b < 8; b++) xn[b] = src[b * 512 + (kc + 1) * 32];
        }
        #pragma unroll
        for (int b = 0; b < 8; b++) {
            #pragma unroll
            for (int r = 0; r < 4; r++) acc[r][b] = ffma2(aa[r], xv[b], acc[r][b]);
        }
        if (kc < 15) {
            #pragma unroll
            for (int b = 0; b < 8; b++) xv[b] = xn[b];
        }
    }

    #pragma unroll
    for (int off = 16; off > 0; off >>= 1) {
        #pragma unroll
        for (int r = 0; r < 4; r++)
            #pragma unroll
            for (int b = 0; b < 8; b++)
                acc[r][b] = fadd2(acc[r][b], __shfl_xor_sync(0xffffffffu, acc[r][b], off));
    }
    if (lane == 0) {
        #pragma unroll
        for (int r = 0; r < 4; r++)
            #pragma unroll
            for (int b = 0; b < 8; b++)
                gates2[(((khalf * 4 + gate) * 4) + r) * 8 + b] = acc[r][b];
    }
    __syncthreads();

    // ---- pointwise epilogue: 4 j x 8 b2 = 32 threads ----
    if (tid < 32) {
        int jl = tid >> 3, b2l = tid & 7;
        int b2 = bhalf * 8 + b2l;
        int j = j0 + jl;
        float gv0[4], gv1[4];
        #pragma unroll
        for (int g = 0; g < 4; g++) {
            u64 s = fadd2(gates2[((0 * 4 + g) * 4 + jl) * 8 + b2l],
                          gates2[((1 * 4 + g) * 4 + jl) * 8 + b2l]);
            float lo, hi; upk2(s, lo, hi);
            float bb = bih[l * 2048 + g * 512 + j] + bhh[l * 2048 + g * 512 + j];
            gv0[g] = lo + bb; gv1[g] = hi + bb;
        }
        float c0, c1; upk2(g_c2[l][b2][j], c0, c1);

        float i0 = sigmoidf_(gv0[0]), f0 = sigmoidf_(gv0[1]);
        float gg0 = tanhf(gv0[2]),   o0 = sigmoidf_(gv0[3]);
        float cn0 = f0 * c0 + i0 * gg0;
        float h0 = o0 * tanhf(cn0);

        float i1 = sigmoidf_(gv1[0]), f1 = sigmoidf_(gv1[1]);
        float gg1 = tanhf(gv1[2]),   o1 = sigmoidf_(gv1[3]);
        float cn1 = f1 * c1 + i1 * gg1;
        float h1 = o1 * tanhf(cn1);

        if (l < 3) {
            g_x[par][l + 1][b2][j] = pk2(h0, h1);
        } else {
            int b0 = 2 * b2;                         // fp16 operand for proj, direct
            g_Hs[((size_t)t * 32 + b0) * 512 + j] = __float2half_rn(h0);
            g_Hs[((size_t)t * 32 + b0 + 1) * 512 + j] = __float2half_rn(h1);
        }
        g_hb[par ^ 1][l][b2][j] = pk2(clip50(h0), clip50(h1));
        g_c2[l][b2][j] = pk2(clip50(cn0), clip50(cn1));
    }
}

// ================= mma.sync fp16 projection (single pass) =================
// C[1664,32000] = A @ W^T, K=512 (8 chunks of 64).
// BM=BN=128, BK=64 (128B rows, XOR swizzle), 8 warps (4m x 2n), warp tile 32x64.
__global__ __launch_bounds__(256) void proj_mma(
    const float* __restrict__ bout, float* __restrict__ out)
{
    extern __shared__ __align__(16) unsigned char ps[];
    const uint32_t sb = s2u(ps);
    const int tid = threadIdx.x, lane = tid & 31, wid = tid >> 5;
    const int wm = wid & 3, wn = wid >> 2;
    const int bm = blockIdx.y * 128, bn = blockIdx.x * 128;

    const uint32_t Ab[2] = {sb, sb + 16384};
    const uint32_t Bb[2] = {sb + 32768, sb + 49152};

    float acc[2][8][4];
    #pragma unroll
    for (int f = 0; f < 2; f++)
        #pragma unroll
        for (int p = 0; p < 8; p++)
            #pragma unroll
            for (int q = 0; q < 4; q++) acc[f][p][q] = 0.0f;

    const int sr = tid >> 3, su = tid & 7;

    // prologue: chunk 0
    #pragma unroll
    for (int i = 0; i < 4; i++) {
        int r = sr + i * 32;
        cpasync16(Ab[0] + r * 128 + ((su ^ (r & 7)) << 4),
                  g_Hs + (size_t)(bm + r) * 512 + su * 8);
        cpasync16(Bb[0] + r * 128 + ((su ^ (r & 7)) << 4),
                  g_Ws + (size_t)(bn + r) * 512 + su * 8);
    }
    cp_commit();

    for (int c = 0; c < 8; c++) {
        if (c + 1 < 8) {
            int k0 = (c + 1) * 64;
            uint32_t da = Ab[(c + 1) & 1], db = Bb[(c + 1) & 1];
            #pragma unroll
            for (int i = 0; i < 4; i++) {
                int r = sr + i * 32;
                cpasync16(da + r * 128 + ((su ^ (r & 7)) << 4),
                          g_Hs + (size_t)(bm + r) * 512 + k0 + su * 8);
                cpasync16(db + r * 128 + ((su ^ (r & 7)) << 4),
                          g_Ws + (size_t)(bn + r) * 512 + k0 + su * 8);
            }
        }
        cp_commit();
        cp_wait1();
        __syncthreads();

        const uint32_t Abase = Ab[c & 1], Bbase = Bb[c & 1];
        const int jA = lane >> 3;
        #pragma unroll
        for (int q = 0; q < 4; q++) {
            uint32_t a[2][4];
            #pragma unroll
            for (int f = 0; f < 2; f++) {
                int r = wm * 32 + f * 16 + (lane & 7) + ((jA & 1) << 3);
                int uu = 2 * q + (jA >> 1);
                uint32_t ad = Abase + r * 128 + ((uu ^ (r & 7)) << 4);
                LDMX4(a[f][0], a[f][1], a[f][2], a[f][3], ad);
            }
            uint32_t b[8][2];
            #pragma unroll
            for (int fp = 0; fp < 4; fp++) {
                int r = wn * 64 + fp * 16 + (lane & 7) + ((jA >> 1) << 3);
                int uu = 2 * q + (jA & 1);
                uint32_t bd = Bbase + r * 128 + ((uu ^ (r & 7)) << 4);
                LDMX4(b[2 * fp][0], b[2 * fp][1], b[2 * fp + 1][0], b[2 * fp + 1][1], bd);
            }
            #pragma unroll
            for (int f = 0; f < 2; f++)
                #pragma unroll
                for (int p = 0; p < 8; p++)
                    mma16816(acc[f][p], a[f], b[p]);
        }
        __syncthreads();
    }

    // epilogue: C[m][n] + bias, remap m=(t*32+b) -> out[b][t][:]
    #pragma unroll
    for (int f = 0; f < 2; f++) {
        int m0 = bm + wm * 32 + f * 16 + (lane >> 2);
        #pragma unroll
        for (int p = 0; p < 8; p++) {
            int n = bn + wn * 64 + p * 8 + 2 * (lane & 3);
            float2 bo = *(const float2*)&bout[n];
            int m = m0;
            if (m < 1632) {
                int tt = m >> 5, b = m & 31;
                float2 r0 = make_float2(acc[f][p][0] + bo.x, acc[f][p][1] + bo.y);
                *(float2*)&out[(size_t)b * NTT * NV + (size_t)tt * NV + n] = r0;
            }
            m = m0 + 8;
            if (m < 1632) {
                int tt = m >> 5, b = m & 31;
                float2 r1 = make_float2(acc[f][p][2] + bo.x, acc[f][p][3] + bo.y);
                *(float2*)&out[(size_t)b * NTT * NV + (size_t)tt * NV + n] = r1;
            }
        }
    }
}

// ================= final hidden state tail =================
__global__ void write_hfin(float* __restrict__ out) {
    int idx = blockIdx.x * blockDim.x + threadIdx.x;   // 65536
    int l = idx >> 14, b = (idx >> 9) & 31, j = idx & 511;
    float lo, hi; upk2(g_hb[1][l][b >> 1][j], lo, hi);
    out[(size_t)NB * NTT * NV + idx] = (b & 1) ? hi : lo;
}

extern "C" void kernel_launch(void* const* d_in, const int* in_sizes, int n_in,
                              void* d_out, int out_size)
{
    (void)in_sizes; (void)n_in; (void)out_size;
    const float* dh   = (const float*)d_in[1];
    const float* dc   = (const float*)d_in[2];
    const int*   tgt  = (const int*)  d_in[3];
    const float* emb  = (const float*)d_in[4];
    const float* Wih  = (const float*)d_in[5];
    const float* Whh  = (const float*)d_in[6];
    const float* bih  = (const float*)d_in[7];
    const float* bhh  = (const float*)d_in[8];
    const float* Wout = (const float*)d_in[9];
    const float* bout = (const float*)d_in[10];
    float* out = (float*)d_out;

    const int SMEM_PROJ = 65536;
    cudaFuncSetAttribute(proj_mma, cudaFuncAttributeMaxDynamicSharedMemorySize, SMEM_PROJ);

    init_pair<<<128, 256>>>(dh, dc);
    init_emb<<<1632, 256>>>(emb, tgt);
    conv_w<<<8000, 256>>>(Wout);

    for (int d = 0; d < NDIAG; d++) {
        int lmin = (d > NTT - 1) ? d - (NTT - 1) : 0;
        int lmax = (d < NL - 1) ? d : NL - 1;
        int ns = lmax - lmin + 1;
        lstm_diag<<<256 * ns, 256>>>(d, Wih, Whh, bih, bhh);
    }

    proj_mma<<<dim3(250, 13), 256, SMEM_PROJ>>>(bout, out);
    write_hfin<<<256, 256>>>(out);
}